// round 13
// baseline (speedup 1.0000x reference)
#include <cuda_runtime.h>
#include <cuda_fp16.h>
#include <cstdint>

#define B_ 8
#define E_ 2048
#define N_ 2048
#define F_ 128

// Y = X @ W^T stored transposed [b][f][n], single fp16 (device scratch).
__device__ __align__(16) __half g_Y[B_ * F_ * N_];

extern __shared__ __align__(16) char g_smem[];

// ---------------- helpers ----------------
__device__ __forceinline__ uint32_t smem_u32(const void* p) {
    uint32_t a;
    asm("{ .reg .u64 t; cvta.to.shared.u64 t, %1; cvt.u32.u64 %0, t; }" : "=r"(a) : "l"(p));
    return a;
}
__device__ __forceinline__ uint32_t h2_as_u32(__half2 h) {
    uint32_t u;
    asm("mov.b32 %0, %1;" : "=r"(u) : "r"(*(uint32_t*)&h));
    return u;
}
__device__ __forceinline__ float4 ldcs4(const float* p) {
    float4 v;
    asm("ld.global.cs.v4.f32 {%0,%1,%2,%3}, [%4];"
        : "=f"(v.x), "=f"(v.y), "=f"(v.z), "=f"(v.w) : "l"(p));
    return v;
}
#define SWZ(x) ((x) ^ (((x) >> 3) & 0x70))

#define CP16(dst, src) \
    asm volatile("cp.async.ca.shared.global [%0], [%1], 16;" :: "r"(dst), "l"(src))
#define CP_COMMIT() asm volatile("cp.async.commit_group;" ::: "memory")
#define CP_WAIT1()  asm volatile("cp.async.wait_group 1;" ::: "memory")
#define CP_WAIT0()  asm volatile("cp.async.wait_group 0;" ::: "memory")

#define LDSM_X4(r0, r1, r2, r3, addr) \
    asm volatile("ldmatrix.sync.aligned.m8n8.x4.shared.b16 {%0,%1,%2,%3}, [%4];" \
                 : "=r"(r0), "=r"(r1), "=r"(r2), "=r"(r3) : "r"(addr))

#define MMA_F16(d, a, b0, b1) \
    asm volatile("mma.sync.aligned.m16n8k16.row.col.f32.f16.f16.f32 " \
                 "{%0,%1,%2,%3}, {%4,%5,%6,%7}, {%8,%9}, {%0,%1,%2,%3};" \
                 : "+f"((d)[0]), "+f"((d)[1]), "+f"((d)[2]), "+f"((d)[3]) \
                 : "r"((a)[0]), "r"((a)[1]), "r"((a)[2]), "r"((a)[3]), \
                   "r"(b0), "r"(b1))

__device__ __forceinline__ void sts128(uint32_t a, uint4 v) {
    asm volatile("st.shared.v4.b32 [%0], {%1, %2, %3, %4};"
                 :: "r"(a), "r"(v.x), "r"(v.y), "r"(v.z), "r"(v.w));
}
__device__ __forceinline__ uint32_t mask2(float x, float y) {
    return (x == -1.f ? 0x3C00u : 0u) | (y == -1.f ? 0x3C000000u : 0u);
}

// ---------------- Prologue: Y = X @ W^T, fp16, transposed store ----------------
// grid 256 (8 b x 32 n-tiles of 64), 256 thr, 2 CTAs/SM. Per-thread 4n x 8f.
#define PSX 68
#define PSW 132
__global__ void __launch_bounds__(256, 2) v2h_prologue(const float* __restrict__ X,
                                                       const float* __restrict__ W) {
    float* sXT = (float*)g_smem;           // [64 k][PSX]  (64 n cols)
    float* sWT = sXT + 64 * PSX;           // [64 k][PSW]  (128 f cols)
    int t = threadIdx.x;
    int b = blockIdx.x >> 5, n0 = (blockIdx.x & 31) << 6;
    int xrow = t & 63,  xkc = (t >> 6) * 16;   // 4 thr/row, 16 k each
    int wrow = t & 127, wkc = (t >> 7) * 32;   // 2 thr/row, 32 k each
    int tn = t & 15, tf = t >> 4;

    float acc[4][8];
#pragma unroll
    for (int i = 0; i < 4; i++)
#pragma unroll
        for (int j = 0; j < 8; j++) acc[i][j] = 0.f;

#pragma unroll
    for (int chunk = 0; chunk < 2; chunk++) {
        int k0 = chunk * 64;
        if (chunk) __syncthreads();
        const float* xp = X + ((size_t)(b * N_ + n0 + xrow)) * F_ + k0 + xkc;
        const float* wp = W + (size_t)wrow * F_ + k0 + wkc;
#pragma unroll
        for (int q = 0; q < 4; q++) {
            float4 v = *(const float4*)(xp + q * 4);
            int k = xkc + q * 4;
            sXT[(k + 0) * PSX + xrow] = v.x; sXT[(k + 1) * PSX + xrow] = v.y;
            sXT[(k + 2) * PSX + xrow] = v.z; sXT[(k + 3) * PSX + xrow] = v.w;
        }
#pragma unroll
        for (int q = 0; q < 8; q++) {
            float4 v = *(const float4*)(wp + q * 4);
            int k = wkc + q * 4;
            sWT[(k + 0) * PSW + wrow] = v.x; sWT[(k + 1) * PSW + wrow] = v.y;
            sWT[(k + 2) * PSW + wrow] = v.z; sWT[(k + 3) * PSW + wrow] = v.w;
        }
        __syncthreads();
#pragma unroll 4
        for (int k = 0; k < 64; k++) {
            float4 xv = *(const float4*)&sXT[k * PSX + tn * 4];
            float4 w0 = *(const float4*)&sWT[k * PSW + tf * 8];
            float4 w1 = *(const float4*)&sWT[k * PSW + tf * 8 + 4];
            float xr[4] = {xv.x, xv.y, xv.z, xv.w};
            float wr[8] = {w0.x, w0.y, w0.z, w0.w, w1.x, w1.y, w1.z, w1.w};
#pragma unroll
            for (int i = 0; i < 4; i++)
#pragma unroll
                for (int j = 0; j < 8; j++) acc[i][j] = fmaf(xr[i], wr[j], acc[i][j]);
        }
    }
#pragma unroll
    for (int j = 0; j < 8; j++) {
        uint2 u;
        u.x = h2_as_u32(__floats2half2_rn(acc[0][j], acc[1][j]));
        u.y = h2_as_u32(__floats2half2_rn(acc[2][j], acc[3][j]));
        *(uint2*)(g_Y + ((size_t)(b * F_ + tf * 8 + j)) * N_ + n0 + tn * 4) = u;
    }
}

// ---------------- Main: out = relu((mask @ Y)/norm + b) ----------------
// grid 256 = b*32 + etile(64 rows); 256 thr = 8 warps (2M x 4N), warp tile 32x32.
// 2 CTAs/SM. 32 stages of K=64. ONE __syncthreads per stage:
//   Y triple-buffered cp.async (issued 2 ahead), mask STS for s+1 written during s,
//   adj LDG prefetched 2 ahead (streaming .cs).
__global__ void __launch_bounds__(256, 2) v2h_main(const float* __restrict__ adj,
                                                   const float* __restrict__ bias,
                                                   float* __restrict__ out) {
    uint32_t sb = smem_u32(g_smem);
    float* sNorm = (float*)g_smem;                       // 64 floats
    const uint32_t tb = (sb + 256u + 1023u) & ~1023u;
    const uint32_t aBase = tb;                           // 2 x 8192   mask fp16
    const uint32_t yBase = tb + 16384u;                  // 3 x 16384  Y fp16
    int t = threadIdx.x, lid = t & 31, wid = t >> 5;
    int warpM = wid >> 2, warpN = wid & 3;               // 2 x 4
    int b = blockIdx.x >> 5, e0 = (blockIdx.x & 31) << 6;

    int r = t >> 2, seg = t & 3;                          // convert: 4 thr/row, 16 k each
    const float* ap = adj + ((size_t)(b * E_ + e0 + r)) * N_ + seg * 16;
    const char* YG = (const char*)(g_Y + (size_t)b * F_ * N_);
    const uint32_t stsOff = (uint32_t)(r * 128 + seg * 32);

    int cnt = 0;
    float4 ra[4];

    // ---- convert+STS closure (stage tag = buffer half) ----
#define CONVERT_STS(abuf_)                                                        \
    do {                                                                          \
        float4 v0 = ra[0], v1 = ra[1], v2 = ra[2], v3 = ra[3];                    \
        cnt += (v0.x == -1.f) + (v0.y == -1.f) + (v0.z == -1.f) + (v0.w == -1.f)  \
             + (v1.x == -1.f) + (v1.y == -1.f) + (v1.z == -1.f) + (v1.w == -1.f)  \
             + (v2.x == -1.f) + (v2.y == -1.f) + (v2.z == -1.f) + (v2.w == -1.f)  \
             + (v3.x == -1.f) + (v3.y == -1.f) + (v3.z == -1.f) + (v3.w == -1.f); \
        uint4 u0, u1;                                                             \
        u0.x = mask2(v0.x, v0.y); u0.y = mask2(v0.z, v0.w);                       \
        u0.z = mask2(v1.x, v1.y); u0.w = mask2(v1.z, v1.w);                       \
        u1.x = mask2(v2.x, v2.y); u1.y = mask2(v2.z, v2.w);                       \
        u1.z = mask2(v3.x, v3.y); u1.w = mask2(v3.z, v3.w);                       \
        sts128((abuf_) + SWZ(stsOff), u0);                                        \
        sts128((abuf_) + SWZ(stsOff + 16u), u1);                                  \
    } while (0)

#define CP_Y(stage_)                                                              \
    do {                                                                          \
        uint32_t yb_ = yBase + (uint32_t)((stage_) % 3) * 16384u;                 \
        size_t ko_ = (size_t)(stage_) * 64;                                       \
        _Pragma("unroll")                                                         \
        for (int i_ = 0; i_ < 4; i_++) {                                          \
            int cid_ = t + i_ * 256, rw_ = cid_ >> 3, j_ = cid_ & 7;              \
            CP16(yb_ + SWZ((uint32_t)(rw_ * 128 + j_ * 16)),                      \
                 YG + ((size_t)rw_ * N_ + ko_ + j_ * 8) * 2);                     \
        }                                                                         \
        CP_COMMIT();                                                              \
    } while (0)

    // ---- prologue of pipeline ----
#pragma unroll
    for (int q = 0; q < 4; q++) ra[q] = ldcs4(ap + q * 4);   // stage 0
    CONVERT_STS(aBase);                                      // mask0 -> abuf0
    CP_Y(0);
    ap += 64;
#pragma unroll
    for (int q = 0; q < 4; q++) ra[q] = ldcs4(ap + q * 4);   // stage 1
    CP_Y(1);

    float acc[2][4][4];
#pragma unroll
    for (int m = 0; m < 2; m++)
#pragma unroll
        for (int n = 0; n < 4; n++)
#pragma unroll
            for (int v = 0; v < 4; v++) acc[m][n][v] = 0.f;

    const uint32_t r16 = (uint32_t)(lid & 15), kb0 = (uint32_t)(lid >> 4);

    for (int s = 0; s < 32; s++) {
        uint32_t aB = aBase + (uint32_t)(s & 1) * 8192u;
        uint32_t yB = yBase + (uint32_t)(s % 3) * 16384u;
        if (s < 31) CP_WAIT1(); else CP_WAIT0();   // Y_s complete
        __syncthreads();                            // everything for stage s visible;
                                                    // buffers for s+1/s+2 now free
        if (s < 31) CONVERT_STS(aBase + (uint32_t)((s + 1) & 1) * 8192u);
        if (s < 30) {
            ap += 64;
#pragma unroll
            for (int q = 0; q < 4; q++) ra[q] = ldcs4(ap + q * 4);  // stage s+2
            CP_Y(s + 2);
        }

#pragma unroll
        for (int kb = 0; kb < 4; kb++) {
            uint32_t koffb = ((uint32_t)kb * 2 + kb0) * 16;
            uint32_t a_[2][4];
#pragma unroll
            for (int mt = 0; mt < 2; mt++) {
                uint32_t row = (uint32_t)(warpM * 32 + mt * 16) + r16;
                LDSM_X4(a_[mt][0], a_[mt][1], a_[mt][2], a_[mt][3],
                        aB + SWZ(row * 128 + koffb));
            }
            uint32_t bh[2][4];
#pragma unroll
            for (int g = 0; g < 2; g++) {
                uint32_t row = (uint32_t)(warpN * 32 + g * 16) + r16;
                LDSM_X4(bh[g][0], bh[g][1], bh[g][2], bh[g][3],
                        yB + SWZ(row * 128 + koffb));
            }
#pragma unroll
            for (int mt = 0; mt < 2; mt++)
#pragma unroll
                for (int g = 0; g < 2; g++) {
                    MMA_F16(acc[mt][2 * g],     a_[mt], bh[g][0], bh[g][2]);
                    MMA_F16(acc[mt][2 * g + 1], a_[mt], bh[g][1], bh[g][3]);
                }
        }
    }

    // norm: quad-reduce (4 threads per row share r = t>>2)
    {
        int c = cnt;
        c += __shfl_xor_sync(0xFFFFFFFFu, c, 1);
        c += __shfl_xor_sync(0xFFFFFFFFu, c, 2);
        if ((lid & 3) == 0) sNorm[r] = (float)(c ? c : 1);
    }
    __syncthreads();

#pragma unroll
    for (int mt = 0; mt < 2; mt++) {
        int lr = warpM * 32 + mt * 16 + (lid >> 2);
        float i0 = 1.0f / sNorm[lr];
        float i1 = 1.0f / sNorm[lr + 8];
        float* o0 = out + ((size_t)(b * E_ + e0 + lr)) * F_;
        float* o1 = o0 + 8 * F_;
#pragma unroll
        for (int nt = 0; nt < 4; nt++) {
            int col = warpN * 32 + nt * 8 + (lid & 3) * 2;
            float2 bb = *(const float2*)(bias + col);
            float* d = acc[mt][nt];
            float2 v0, v1;
            v0.x = fmaxf(fmaf(d[0], i0, bb.x), 0.f);
            v0.y = fmaxf(fmaf(d[1], i0, bb.y), 0.f);
            v1.x = fmaxf(fmaf(d[2], i1, bb.x), 0.f);
            v1.y = fmaxf(fmaf(d[3], i1, bb.y), 0.f);
            *(float2*)(o0 + col) = v0;
            *(float2*)(o1 + col) = v1;
        }
    }
}

extern "C" void kernel_launch(void* const* d_in, const int* in_sizes, int n_in,
                              void* d_out, int out_size) {
    const float* X    = (const float*)d_in[0];  // [B,N,F]
    const float* adj  = (const float*)d_in[1];  // [B,E,N]
    const float* W    = (const float*)d_in[2];  // [F,F]
    const float* bias = (const float*)d_in[3];  // [F]
    float* out = (float*)d_out;                 // [B,E,F]
    (void)in_sizes; (void)n_in; (void)out_size;

    const int smem_pro  = 64 * (PSX + PSW) * 4;                // 51200
    const int smem_main = 1024 + 1024 + 2 * 8192 + 3 * 16384;  // 67584
    cudaFuncSetAttribute(v2h_prologue, cudaFuncAttributeMaxDynamicSharedMemorySize, smem_pro);
    cudaFuncSetAttribute(v2h_main,     cudaFuncAttributeMaxDynamicSharedMemorySize, smem_main);

    v2h_prologue<<<256, 256, smem_pro>>>(X, W);
    v2h_main<<<256, 256, smem_main>>>(adj, bias, out);
}

// round 14
// speedup vs baseline: 1.2496x; 1.2496x over previous
#include <cuda_runtime.h>
#include <cuda_fp16.h>
#include <cstdint>

#define B_ 8
#define E_ 2048
#define N_ 2048
#define F_ 128

// Y = X @ W^T stored transposed [b][f][n], single fp16 (device scratch).
__device__ __align__(16) __half g_Y[B_ * F_ * N_];

extern __shared__ __align__(16) char g_smem[];

// ---------------- helpers ----------------
__device__ __forceinline__ uint32_t smem_u32(const void* p) {
    uint32_t a;
    asm("{ .reg .u64 t; cvta.to.shared.u64 t, %1; cvt.u32.u64 %0, t; }" : "=r"(a) : "l"(p));
    return a;
}
__device__ __forceinline__ uint32_t h2_as_u32(__half2 h) {
    uint32_t u;
    asm("mov.b32 %0, %1;" : "=r"(u) : "r"(*(uint32_t*)&h));
    return u;
}
__device__ __forceinline__ float4 ldcs4(const float* p) {
    float4 v;
    asm("ld.global.cs.v4.f32 {%0,%1,%2,%3}, [%4];"
        : "=f"(v.x), "=f"(v.y), "=f"(v.z), "=f"(v.w) : "l"(p));
    return v;
}
#define SWZ(x) ((x) ^ (((x) >> 3) & 0x70))

#define CP16(dst, src) \
    asm volatile("cp.async.ca.shared.global [%0], [%1], 16;" :: "r"(dst), "l"(src))
#define CP_COMMIT() asm volatile("cp.async.commit_group;" ::: "memory")
#define CP_WAIT1()  asm volatile("cp.async.wait_group 1;" ::: "memory")
#define CP_WAIT0()  asm volatile("cp.async.wait_group 0;" ::: "memory")

#define LDSM_X4(r0, r1, r2, r3, addr) \
    asm volatile("ldmatrix.sync.aligned.m8n8.x4.shared.b16 {%0,%1,%2,%3}, [%4];" \
                 : "=r"(r0), "=r"(r1), "=r"(r2), "=r"(r3) : "r"(addr))

#define MMA_F16(d, a, b0, b1) \
    asm volatile("mma.sync.aligned.m16n8k16.row.col.f32.f16.f16.f32 " \
                 "{%0,%1,%2,%3}, {%4,%5,%6,%7}, {%8,%9}, {%0,%1,%2,%3};" \
                 : "+f"((d)[0]), "+f"((d)[1]), "+f"((d)[2]), "+f"((d)[3]) \
                 : "r"((a)[0]), "r"((a)[1]), "r"((a)[2]), "r"((a)[3]), \
                   "r"(b0), "r"(b1))

__device__ __forceinline__ void sts64(uint32_t a, uint32_t x, uint32_t y) {
    asm volatile("st.shared.v2.b32 [%0], {%1, %2};" :: "r"(a), "r"(x), "r"(y));
}
__device__ __forceinline__ void sts128(uint32_t a, uint4 v) {
    asm volatile("st.shared.v4.b32 [%0], {%1, %2, %3, %4};"
                 :: "r"(a), "r"(v.x), "r"(v.y), "r"(v.z), "r"(v.w));
}
__device__ __forceinline__ uint32_t mask2(float x, float y) {
    return (x == -1.f ? 0x3C00u : 0u) | (y == -1.f ? 0x3C000000u : 0u);
}

// ---------------- Prologue: Y = fp16(X) @ fp16(W)^T via mma.sync ----------------
// D = W @ X^T so D rows = f -> direct transposed store to Y[b][f][n].
// grid 128 = 8 b x 16 n-tiles(128); 256 thr = 8 warps (2Mf x 4Nn), warp tile 64f x 32n.
// K=128 in 8 k16 steps; smem Wh + Xh as 2x[128rows][64k] fp16 SW128 buffers each.
__global__ void __launch_bounds__(256) v2h_prologue(const float* __restrict__ X,
                                                    const float* __restrict__ W) {
    uint32_t sb = smem_u32(g_smem);
    const uint32_t WhB = sb;             // 2 x 16384
    const uint32_t XhB = sb + 32768u;    // 2 x 16384
    int t = threadIdx.x, lid = t & 31, wid = t >> 5;
    int warpM = wid >> 2, warpN = wid & 3;
    int b = blockIdx.x >> 4, n0 = (blockIdx.x & 15) << 7;

    // load + fp16 convert: 2 thr/row, 64 k each
    {
        int row = t >> 1, seg = t & 1;
        const float* wp = W + (size_t)row * F_ + seg * 64;
        const float* xp = X + ((size_t)(b * N_ + n0 + row)) * F_ + seg * 64;
        uint32_t wdst = WhB + (uint32_t)seg * 16384u;
        uint32_t xdst = XhB + (uint32_t)seg * 16384u;
#pragma unroll
        for (int q = 0; q < 16; q++) {
            float4 wv = ldcs4(wp + q * 4);
            float4 xv = ldcs4(xp + q * 4);
            uint32_t off = SWZ((uint32_t)(row * 128 + q * 8));
            sts64(wdst + off, h2_as_u32(__floats2half2_rn(wv.x, wv.y)),
                              h2_as_u32(__floats2half2_rn(wv.z, wv.w)));
            sts64(xdst + off, h2_as_u32(__floats2half2_rn(xv.x, xv.y)),
                              h2_as_u32(__floats2half2_rn(xv.z, xv.w)));
        }
    }
    __syncthreads();

    float acc[4][4][4];
#pragma unroll
    for (int m = 0; m < 4; m++)
#pragma unroll
        for (int n = 0; n < 4; n++)
#pragma unroll
            for (int v = 0; v < 4; v++) acc[m][n][v] = 0.f;

    const uint32_t r16 = (uint32_t)(lid & 15), kb0 = (uint32_t)(lid >> 4);

#pragma unroll
    for (int kb = 0; kb < 8; kb++) {
        uint32_t kbuf = (uint32_t)(kb >> 2) * 16384u;
        uint32_t ko = (((uint32_t)kb & 3u) * 2u + kb0) * 16u;
        uint32_t bx[2][4];
#pragma unroll
        for (int g = 0; g < 2; g++) {
            uint32_t row = (uint32_t)(warpN * 32 + g * 16) + r16;
            LDSM_X4(bx[g][0], bx[g][1], bx[g][2], bx[g][3],
                    XhB + kbuf + SWZ(row * 128 + ko));
        }
#pragma unroll
        for (int mt = 0; mt < 4; mt++) {
            uint32_t row = (uint32_t)(warpM * 64 + mt * 16) + r16;
            uint32_t aw[4];
            LDSM_X4(aw[0], aw[1], aw[2], aw[3], WhB + kbuf + SWZ(row * 128 + ko));
            MMA_F16(acc[mt][0], aw, bx[0][0], bx[0][2]);
            MMA_F16(acc[mt][1], aw, bx[0][1], bx[0][3]);
            MMA_F16(acc[mt][2], aw, bx[1][0], bx[1][2]);
            MMA_F16(acc[mt][3], aw, bx[1][1], bx[1][3]);
        }
    }

    // direct transposed store: d0,d1 cols n,n+1 at row f; d2,d3 at f+8
    __half* Yb = g_Y + (size_t)b * F_ * N_;
#pragma unroll
    for (int mt = 0; mt < 4; mt++) {
        int f = warpM * 64 + mt * 16 + (lid >> 2);
#pragma unroll
        for (int nt = 0; nt < 4; nt++) {
            int n = n0 + warpN * 32 + nt * 8 + (lid & 3) * 2;
            float* d = acc[mt][nt];
            *(uint32_t*)(Yb + (size_t)f * N_ + n) =
                h2_as_u32(__floats2half2_rn(d[0], d[1]));
            *(uint32_t*)(Yb + (size_t)(f + 8) * N_ + n) =
                h2_as_u32(__floats2half2_rn(d[2], d[3]));
        }
    }
}

// ---------------- Main: out = relu((mask @ Y)/norm + b)  (unchanged from R13) ----------------
__global__ void __launch_bounds__(256, 2) v2h_main(const float* __restrict__ adj,
                                                   const float* __restrict__ bias,
                                                   float* __restrict__ out) {
    uint32_t sb = smem_u32(g_smem);
    float* sNorm = (float*)g_smem;
    const uint32_t tb = (sb + 256u + 1023u) & ~1023u;
    const uint32_t aBase = tb;                           // 2 x 8192
    const uint32_t yBase = tb + 16384u;                  // 3 x 16384
    int t = threadIdx.x, lid = t & 31, wid = t >> 5;
    int warpM = wid >> 2, warpN = wid & 3;
    int b = blockIdx.x >> 5, e0 = (blockIdx.x & 31) << 6;

    int r = t >> 2, seg = t & 3;
    const float* ap = adj + ((size_t)(b * E_ + e0 + r)) * N_ + seg * 16;
    const char* YG = (const char*)(g_Y + (size_t)b * F_ * N_);
    const uint32_t stsOff = (uint32_t)(r * 128 + seg * 32);

    int cnt = 0;
    float4 ra[4];

#define CONVERT_STS(abuf_)                                                        \
    do {                                                                          \
        float4 v0 = ra[0], v1 = ra[1], v2 = ra[2], v3 = ra[3];                    \
        cnt += (v0.x == -1.f) + (v0.y == -1.f) + (v0.z == -1.f) + (v0.w == -1.f)  \
             + (v1.x == -1.f) + (v1.y == -1.f) + (v1.z == -1.f) + (v1.w == -1.f)  \
             + (v2.x == -1.f) + (v2.y == -1.f) + (v2.z == -1.f) + (v2.w == -1.f)  \
             + (v3.x == -1.f) + (v3.y == -1.f) + (v3.z == -1.f) + (v3.w == -1.f); \
        uint4 u0, u1;                                                             \
        u0.x = mask2(v0.x, v0.y); u0.y = mask2(v0.z, v0.w);                       \
        u0.z = mask2(v1.x, v1.y); u0.w = mask2(v1.z, v1.w);                       \
        u1.x = mask2(v2.x, v2.y); u1.y = mask2(v2.z, v2.w);                       \
        u1.z = mask2(v3.x, v3.y); u1.w = mask2(v3.z, v3.w);                       \
        sts128((abuf_) + SWZ(stsOff), u0);                                        \
        sts128((abuf_) + SWZ(stsOff + 16u), u1);                                  \
    } while (0)

#define CP_Y(stage_)                                                              \
    do {                                                                          \
        uint32_t yb_ = yBase + (uint32_t)((stage_) % 3) * 16384u;                 \
        size_t ko_ = (size_t)(stage_) * 64;                                       \
        _Pragma("unroll")                                                         \
        for (int i_ = 0; i_ < 4; i_++) {                                          \
            int cid_ = t + i_ * 256, rw_ = cid_ >> 3, j_ = cid_ & 7;              \
            CP16(yb_ + SWZ((uint32_t)(rw_ * 128 + j_ * 16)),                      \
                 YG + ((size_t)rw_ * N_ + ko_ + j_ * 8) * 2);                     \
        }                                                                         \
        CP_COMMIT();                                                              \
    } while (0)

#pragma unroll
    for (int q = 0; q < 4; q++) ra[q] = ldcs4(ap + q * 4);
    CONVERT_STS(aBase);
    CP_Y(0);
    ap += 64;
#pragma unroll
    for (int q = 0; q < 4; q++) ra[q] = ldcs4(ap + q * 4);
    CP_Y(1);

    float acc[2][4][4];
#pragma unroll
    for (int m = 0; m < 2; m++)
#pragma unroll
        for (int n = 0; n < 4; n++)
#pragma unroll
            for (int v = 0; v < 4; v++) acc[m][n][v] = 0.f;

    const uint32_t r16 = (uint32_t)(lid & 15), kb0 = (uint32_t)(lid >> 4);

    for (int s = 0; s < 32; s++) {
        uint32_t aB = aBase + (uint32_t)(s & 1) * 8192u;
        uint32_t yB = yBase + (uint32_t)(s % 3) * 16384u;
        if (s < 31) CP_WAIT1(); else CP_WAIT0();
        __syncthreads();
        if (s < 31) CONVERT_STS(aBase + (uint32_t)((s + 1) & 1) * 8192u);
        if (s < 30) {
            ap += 64;
#pragma unroll
            for (int q = 0; q < 4; q++) ra[q] = ldcs4(ap + q * 4);
            CP_Y(s + 2);
        }

#pragma unroll
        for (int kb = 0; kb < 4; kb++) {
            uint32_t koffb = ((uint32_t)kb * 2 + kb0) * 16;
            uint32_t a_[2][4];
#pragma unroll
            for (int mt = 0; mt < 2; mt++) {
                uint32_t row = (uint32_t)(warpM * 32 + mt * 16) + r16;
                LDSM_X4(a_[mt][0], a_[mt][1], a_[mt][2], a_[mt][3],
                        aB + SWZ(row * 128 + koffb));
            }
            uint32_t bh[2][4];
#pragma unroll
            for (int g = 0; g < 2; g++) {
                uint32_t row = (uint32_t)(warpN * 32 + g * 16) + r16;
                LDSM_X4(bh[g][0], bh[g][1], bh[g][2], bh[g][3],
                        yB + SWZ(row * 128 + koffb));
            }
#pragma unroll
            for (int mt = 0; mt < 2; mt++)
#pragma unroll
                for (int g = 0; g < 2; g++) {
                    MMA_F16(acc[mt][2 * g],     a_[mt], bh[g][0], bh[g][2]);
                    MMA_F16(acc[mt][2 * g + 1], a_[mt], bh[g][1], bh[g][3]);
                }
        }
    }

    {
        int c = cnt;
        c += __shfl_xor_sync(0xFFFFFFFFu, c, 1);
        c += __shfl_xor_sync(0xFFFFFFFFu, c, 2);
        if ((lid & 3) == 0) sNorm[r] = (float)(c ? c : 1);
    }
    __syncthreads();

#pragma unroll
    for (int mt = 0; mt < 2; mt++) {
        int lr = warpM * 32 + mt * 16 + (lid >> 2);
        float i0 = 1.0f / sNorm[lr];
        float i1 = 1.0f / sNorm[lr + 8];
        float* o0 = out + ((size_t)(b * E_ + e0 + lr)) * F_;
        float* o1 = o0 + 8 * F_;
#pragma unroll
        for (int nt = 0; nt < 4; nt++) {
            int col = warpN * 32 + nt * 8 + (lid & 3) * 2;
            float2 bb = *(const float2*)(bias + col);
            float* d = acc[mt][nt];
            float2 v0, v1;
            v0.x = fmaxf(fmaf(d[0], i0, bb.x), 0.f);
            v0.y = fmaxf(fmaf(d[1], i0, bb.y), 0.f);
            v1.x = fmaxf(fmaf(d[2], i1, bb.x), 0.f);
            v1.y = fmaxf(fmaf(d[3], i1, bb.y), 0.f);
            *(float2*)(o0 + col) = v0;
            *(float2*)(o1 + col) = v1;
        }
    }
}

extern "C" void kernel_launch(void* const* d_in, const int* in_sizes, int n_in,
                              void* d_out, int out_size) {
    const float* X    = (const float*)d_in[0];  // [B,N,F]
    const float* adj  = (const float*)d_in[1];  // [B,E,N]
    const float* W    = (const float*)d_in[2];  // [F,F]
    const float* bias = (const float*)d_in[3];  // [F]
    float* out = (float*)d_out;                 // [B,E,F]
    (void)in_sizes; (void)n_in; (void)out_size;

    const int smem_pro  = 65536;                               // Wh 32K + Xh 32K
    const int smem_main = 1024 + 1024 + 2 * 8192 + 3 * 16384;  // 67584
    cudaFuncSetAttribute(v2h_prologue, cudaFuncAttributeMaxDynamicSharedMemorySize, smem_pro);
    cudaFuncSetAttribute(v2h_main,     cudaFuncAttributeMaxDynamicSharedMemorySize, smem_main);

    v2h_prologue<<<128, 256, smem_pro>>>(X, W);
    v2h_main<<<256, 256, smem_main>>>(adj, bias, out);
}